// round 1
// baseline (speedup 1.0000x reference)
#include <cuda_runtime.h>

// CorrTorch: out[o,z,y,x] = bias[o] + (1/sqrt(32)) * sum_{dz,dy,dx,c}
//     w[o, (dz*9+dy*3+dx)*32 + c] * in1[c,z,y,x] * in2[c, z+dz-1, y+dy-1, x+dx-1]
// with zero padding on in2. Shapes: C=32, D=H=W=64, 27 offsets, 27 outputs.
//
// Strategy (round 0): fp32 CUDA-core GEMM-style kernel.
//  - W staged in SMEM as duplicated {w,w} u64 pairs, o padded 27->28, so the
//    inner o-loop is 13x LDS.128 + 1x LDS.64 (broadcast) per K-element.
//  - Each thread: 4 consecutive-x voxels as 2 packed f32x2 accumulators per
//    output -> 54 fma.rn.f32x2 (108 MACs) per K-element, fma-pipe bound.

#define C_    32
#define NOFF_ 27
#define KDIM  864        // 27*32
#define VOX   262144     // 64^3
#define WS_PITCH 28      // o-dim padded for 16B-aligned LDS.128 pairs

__device__ __forceinline__ unsigned long long pack2(float lo, float hi) {
    unsigned long long r;
    asm("mov.b64 %0, {%1,%2};" : "=l"(r) : "f"(lo), "f"(hi));
    return r;
}
__device__ __forceinline__ void ffma2(unsigned long long& d,
                                      unsigned long long a,
                                      unsigned long long b) {
    asm("fma.rn.f32x2 %0, %1, %2, %0;" : "+l"(d) : "l"(a), "l"(b));
}
__device__ __forceinline__ float2 unpack2(unsigned long long v) {
    float lo, hi;
    asm("mov.b64 {%0,%1}, %2;" : "=f"(lo), "=f"(hi) : "l"(v));
    return make_float2(lo, hi);
}

__global__ void __launch_bounds__(256, 1)
corr_kernel(const float* __restrict__ in1, const float* __restrict__ in2,
            const float* __restrict__ w, const float* __restrict__ bias,
            float* __restrict__ out)
{
    extern __shared__ unsigned long long ws[];   // [KDIM][WS_PITCH] duplicated {w,w}

    const int tid = threadIdx.x;

    // Stage W transposed: ws[i*28 + o] = {w[o*864+i], w[o*864+i]}
    for (int idx = tid; idx < NOFF_ * KDIM; idx += 256) {
        int o = idx / KDIM;
        int i = idx - o * KDIM;
        unsigned int u = __float_as_uint(w[idx]);
        ws[(unsigned)i * WS_PITCH + o] = ((unsigned long long)u << 32) | u;
    }
    __syncthreads();

    // Each block: 1024 consecutive voxels. Each thread: 4 consecutive-x voxels.
    const int base = blockIdx.x * 1024 + tid * 4;
    const int x0 = base & 63;
    const int y  = (base >> 6) & 63;
    const int z  = base >> 12;

    unsigned long long acc[NOFF_][2];
#pragma unroll
    for (int o = 0; o < NOFF_; o++) { acc[o][0] = 0ull; acc[o][1] = 0ull; }

    const float scale = 0.17677669529663688f;   // 1/sqrt(32)

    for (int c = 0; c < C_; c++) {
        const float4 a4 = *reinterpret_cast<const float4*>(in1 + c * VOX + base);
        const float a0 = a4.x * scale, a1 = a4.y * scale;
        const float a2 = a4.z * scale, a3 = a4.w * scale;
        const float* b2 = in2 + c * VOX;

#pragma unroll
        for (int dz = 0; dz < 3; dz++) {
            const int zz = z + dz - 1;
#pragma unroll
            for (int dy = 0; dy < 3; dy++) {
                const int yy = y + dy - 1;
                const bool ok = (zz >= 0) & (zz < 64) & (yy >= 0) & (yy < 64);

                float rr[6];
                if (ok) {
                    const float* row = b2 + (zz << 12) + (yy << 6) + x0;
                    const float4 m = *reinterpret_cast<const float4*>(row);
                    rr[1] = m.x; rr[2] = m.y; rr[3] = m.z; rr[4] = m.w;
                    rr[0] = (x0 > 0)  ? row[-1] : 0.0f;   // x-1 edge (zero pad)
                    rr[5] = (x0 < 60) ? row[4]  : 0.0f;   // x+1 edge (zero pad)
                } else {
                    rr[0] = rr[1] = rr[2] = rr[3] = rr[4] = rr[5] = 0.0f;
                }

#pragma unroll
                for (int dx = 0; dx < 3; dx++) {
                    // products for voxels v=0..3: in1[v]*in2[v+dx-1]
                    const unsigned long long p0 = pack2(a0 * rr[dx],     a1 * rr[dx + 1]);
                    const unsigned long long q0 = pack2(a2 * rr[dx + 2], a3 * rr[dx + 3]);
                    const int i = (dz * 9 + dy * 3 + dx) * C_ + c;
                    const unsigned long long* wr = ws + (unsigned)i * WS_PITCH;
#pragma unroll
                    for (int oo = 0; oo < 13; oo++) {
                        const ulonglong2 wv =
                            *reinterpret_cast<const ulonglong2*>(wr + 2 * oo);
                        ffma2(acc[2 * oo    ][0], wv.x, p0);
                        ffma2(acc[2 * oo    ][1], wv.x, q0);
                        ffma2(acc[2 * oo + 1][0], wv.y, p0);
                        ffma2(acc[2 * oo + 1][1], wv.y, q0);
                    }
                    const unsigned long long wv26 = wr[26];
                    ffma2(acc[26][0], wv26, p0);
                    ffma2(acc[26][1], wv26, q0);
                }
            }
        }
    }

#pragma unroll
    for (int o = 0; o < NOFF_; o++) {
        const float bo = __ldg(bias + o);
        const float2 lo = unpack2(acc[o][0]);
        const float2 hi = unpack2(acc[o][1]);
        const float4 res = make_float4(lo.x + bo, lo.y + bo, hi.x + bo, hi.y + bo);
        *reinterpret_cast<float4*>(out + (unsigned)o * VOX + base) = res;
    }
}

extern "C" void kernel_launch(void* const* d_in, const int* in_sizes, int n_in,
                              void* d_out, int out_size) {
    const float* in1 = (const float*)d_in[0];
    const float* in2 = (const float*)d_in[1];
    const float* w   = (const float*)d_in[2];
    const float* b   = (const float*)d_in[3];
    float* out = (float*)d_out;

    const int smem = KDIM * WS_PITCH * (int)sizeof(unsigned long long); // 193536 B
    cudaFuncSetAttribute(corr_kernel,
                         cudaFuncAttributeMaxDynamicSharedMemorySize, smem);

    corr_kernel<<<VOX / 1024, 256, smem>>>(in1, in2, w, b, out);
}

// round 3
// speedup vs baseline: 1.5087x; 1.5087x over previous
#include <cuda_runtime.h>
#include <cstdint>

// CorrTorch via warp-level tf32 mma.sync (m16n8k8):
//   out[o, v] = bias[o] + sum_{off,c} W'[o, off*32+c] * in1[c,v] * in2[c, v+off]
//   W' = conv_w * (1/sqrt(32)), o padded 27 -> 32.
// Per warp: D[32 vox, 32 out] as 2 m-tiles x 4 n-tiles of m16n8k8.
// A = products (built in registers, tf32-rounded once), B = weight fragments
// (pre-packed per-lane float2 in SMEM).

#define C_    32
#define NOFF_ 27
#define VOX   262144                 // 64^3
#define NCHUNK 108                   // 27 offsets * 4 k8-chunks
#define WF_ELEMS (NCHUNK * 4 * 32)   // 13824 float2 = 110592 B

__device__ float2 WF_g[WF_ELEMS];    // packed tf32 weight fragments

// ---------------- weight staging: scale, pad, tf32-round, fragment-pack ----
__global__ void stage_weights(const float* __restrict__ w) {
    int idx = blockIdx.x * blockDim.x + threadIdx.x;
    if (idx >= WF_ELEMS) return;
    int lane = idx & 31;
    int nt   = (idx >> 5) & 3;
    int chunk = idx >> 7;            // 0..107
    int off = chunk >> 2;            // 0..26
    int cq  = chunk & 3;             // 0..3
    int tg = lane >> 2, tk = lane & 3;
    int o = nt * 8 + tg;
    int k0 = off * 32 + cq * 8;
    const float s = 0.17677669529663688f;  // 1/sqrt(32)
    float b0 = 0.f, b1 = 0.f;
    if (o < NOFF_) {
        b0 = w[o * (NOFF_ * C_) + k0 + tk] * s;
        b1 = w[o * (NOFF_ * C_) + k0 + tk + 4] * s;
    }
    uint32_t u0, u1;
    asm("cvt.rna.tf32.f32 %0, %1;" : "=r"(u0) : "f"(b0));
    asm("cvt.rna.tf32.f32 %0, %1;" : "=r"(u1) : "f"(b1));
    WF_g[idx] = make_float2(__uint_as_float(u0), __uint_as_float(u1));
}

// ---------------- mma helper ----------------
__device__ __forceinline__ void mma_tf32(float* d, uint32_t a0, uint32_t a1,
                                         uint32_t a2, uint32_t a3,
                                         uint32_t b0, uint32_t b1) {
    asm volatile(
        "mma.sync.aligned.m16n8k8.row.col.f32.tf32.tf32.f32 "
        "{%0,%1,%2,%3}, {%4,%5,%6,%7}, {%8,%9}, {%0,%1,%2,%3};"
        : "+f"(d[0]), "+f"(d[1]), "+f"(d[2]), "+f"(d[3])
        : "r"(a0), "r"(a1), "r"(a2), "r"(a3), "r"(b0), "r"(b1));
}
__device__ __forceinline__ uint32_t prod_tf32(float a, float b) {
    uint32_t u;
    float p = a * b;
    asm("cvt.rna.tf32.f32 %0, %1;" : "=r"(u) : "f"(p));
    return u;
}

// ---------------- main kernel ----------------
// Warp = one 32-voxel half-row (fixed z,y; x in [xw0, xw0+32)).
// grid: 8192 half-rows / 8 warps per block = 1024 blocks.
__global__ void __launch_bounds__(256, 2)
corr_mma(const float* __restrict__ in1, const float* __restrict__ in2,
         const float* __restrict__ bias, float* __restrict__ out)
{
    extern __shared__ float2 wfs[];   // [NCHUNK*4*32]

    const int tid = threadIdx.x;
    // stage weight fragments (float4 copies)
    {
        const float4* src = reinterpret_cast<const float4*>(WF_g);
        float4* dst = reinterpret_cast<float4*>(wfs);
        for (int i = tid; i < WF_ELEMS / 2; i += 256) dst[i] = src[i];
    }
    __syncthreads();

    const int lane = tid & 31;
    const int wid  = tid >> 5;
    const int tg = lane >> 2;     // voxel-in-group 0..7
    const int tk = lane & 3;      // k-in-group 0..3

    const int gw  = blockIdx.x * 8 + wid;   // 0..8191
    const int row = gw >> 1;                // 0..4095 (z,y)
    const int xw0 = (gw & 1) << 5;          // 0 or 32
    const int z = row >> 6, y = row & 63;
    const int vbase = (row << 6) + xw0;     // first voxel of this warp

    float acc[2][16];
#pragma unroll
    for (int mt = 0; mt < 2; mt++)
#pragma unroll
        for (int i = 0; i < 16; i++) acc[mt][i] = 0.f;

    // corner-case x predicates (only possible OOB in x)
    const bool corner_lo = (xw0 == 0) && (tg == 0);    // x = -1 when dx==0
    const bool corner_hi = (xw0 == 32) && (tg == 7);   // x = 64 when dx==2

#pragma unroll 1
    for (int cq = 0; cq < 4; cq++) {
        // in1 fragment values for this k-quarter (channels cq*8+tk, +4)
        const float* p1a = in1 + (cq * 8 + tk) * VOX + vbase + tg;
        const float* p1b = p1a + 4 * VOX;
        float a1v[2][4];
#pragma unroll
        for (int mt = 0; mt < 2; mt++) {
            a1v[mt][0] = __ldg(p1a + 16 * mt);
            a1v[mt][1] = __ldg(p1a + 16 * mt + 8);
            a1v[mt][2] = __ldg(p1b + 16 * mt);
            a1v[mt][3] = __ldg(p1b + 16 * mt + 8);
        }

#pragma unroll 1
        for (int off = 0; off < NOFF_; off++) {
            const int dz = off / 9;
            const int rem = off - dz * 9;
            const int dy = rem / 3;
            const int dx = rem - dy * 3;
            const int zz = z + dz - 1, yy = y + dy - 1;
            const bool okzy = ((unsigned)zz < 64u) & ((unsigned)yy < 64u);

            const float* p2a = in2 + (cq * 8 + tk) * VOX
                             + (zz << 12) + (yy << 6) + xw0 + tg + (dx - 1);
            const float* p2b = p2a + 4 * VOX;

            const bool pl = okzy & !(corner_lo & (dx == 0));  // load [0]
            const bool ph = okzy & !(corner_hi & (dx == 2));  // load [24]

            float b2v[2][4];
            b2v[0][0] = pl   ? __ldg(p2a + 0)  : 0.f;
            b2v[0][1] = okzy ? __ldg(p2a + 8)  : 0.f;
            b2v[0][2] = pl   ? __ldg(p2b + 0)  : 0.f;
            b2v[0][3] = okzy ? __ldg(p2b + 8)  : 0.f;
            b2v[1][0] = okzy ? __ldg(p2a + 16) : 0.f;
            b2v[1][1] = ph   ? __ldg(p2a + 24) : 0.f;
            b2v[1][2] = okzy ? __ldg(p2b + 16) : 0.f;
            b2v[1][3] = ph   ? __ldg(p2b + 24) : 0.f;

            // weight fragments for the 4 n-tiles of this chunk
            const float2* wp = wfs + (off * 4 + cq) * 128 + lane;
            uint32_t wb[4][2];
#pragma unroll
            for (int nt = 0; nt < 4; nt++) {
                float2 wv = wp[nt * 32];
                wb[nt][0] = __float_as_uint(wv.x);
                wb[nt][1] = __float_as_uint(wv.y);
            }

#pragma unroll
            for (int mt = 0; mt < 2; mt++) {
                const uint32_t a0 = prod_tf32(a1v[mt][0], b2v[mt][0]);
                const uint32_t a1 = prod_tf32(a1v[mt][1], b2v[mt][1]);
                const uint32_t a2 = prod_tf32(a1v[mt][2], b2v[mt][2]);
                const uint32_t a3 = prod_tf32(a1v[mt][3], b2v[mt][3]);
#pragma unroll
                for (int nt = 0; nt < 4; nt++)
                    mma_tf32(&acc[mt][nt * 4], a0, a1, a2, a3,
                             wb[nt][0], wb[nt][1]);
            }
        }
    }

    // epilogue: D row = voxel, col = output. c0:(tg, tk*2) c1:(tg, tk*2+1)
    //           c2:(tg+8, tk*2) c3:(tg+8, tk*2+1)
#pragma unroll
    for (int nt = 0; nt < 4; nt++) {
        const int o0 = nt * 8 + tk * 2;
        const float bo0 = (o0 < NOFF_)     ? __ldg(bias + o0)     : 0.f;
        const float bo1 = (o0 + 1 < NOFF_) ? __ldg(bias + o0 + 1) : 0.f;
#pragma unroll
        for (int mt = 0; mt < 2; mt++) {
            const int v = vbase + 16 * mt + tg;
            if (o0 < NOFF_) {
                out[o0 * VOX + v]     = acc[mt][nt * 4 + 0] + bo0;
                out[o0 * VOX + v + 8] = acc[mt][nt * 4 + 2] + bo0;
            }
            if (o0 + 1 < NOFF_) {
                out[(o0 + 1) * VOX + v]     = acc[mt][nt * 4 + 1] + bo1;
                out[(o0 + 1) * VOX + v + 8] = acc[mt][nt * 4 + 3] + bo1;
            }
        }
    }
}

extern "C" void kernel_launch(void* const* d_in, const int* in_sizes, int n_in,
                              void* d_out, int out_size) {
    const float* in1 = (const float*)d_in[0];
    const float* in2 = (const float*)d_in[1];
    const float* w   = (const float*)d_in[2];
    const float* b   = (const float*)d_in[3];
    float* out = (float*)d_out;

    stage_weights<<<(WF_ELEMS + 255) / 256, 256>>>(w);

    const int smem = WF_ELEMS * (int)sizeof(float2);   // 110592
    cudaFuncSetAttribute(corr_mma,
                         cudaFuncAttributeMaxDynamicSharedMemorySize, smem);
    corr_mma<<<1024, 256, smem>>>(in1, in2, b, out);
}

// round 4
// speedup vs baseline: 2.6645x; 1.7661x over previous
#include <cuda_runtime.h>
#include <cstdint>

// CorrTorch via warp-level tf32 mma.sync (m16n8k8), x-consecutive lane layout:
//   out[o, v] = bias[o] + sum_{off,c} W'[o, off*32+c] * in1[c,v] * in2[c, v+off]
// Per warp: 32 consecutive-x voxels x 32 outputs. Lane tg owns x = 4tg..4tg+3
// (mt0 rows tg,tg+8 -> 4tg,4tg+1; mt1 -> 4tg+2,4tg+3), so in2 for all three dx
// shifts comes from one LDG.128 + 2 halo scalars per (cq,dz,dy,channel).

#define C_    32
#define NOFF_ 27
#define VOX   262144                 // 64^3
#define NCHUNK 108                   // 27 offsets * 4 k8-chunks
#define WQ_ELEMS (NCHUNK * 64)       // float4 count = 6912 (110592 B)

__device__ float4 WQ_g[WQ_ELEMS];    // packed tf32 weight fragments

// ---------------- weight staging ----------------
// Layout: [(off*4+cq)*64 + h*32 + lane] -> float4
//   h=0: (nt0.b0, nt0.b1, nt1.b0, nt1.b1); h=1: (nt2..., nt3...)
//   b0 = W'[o=nt*8+tg][k0+tk], b1 = W'[o][k0+tk+4], tf32-rounded, o>=27 -> 0.
__global__ void stage_weights(const float* __restrict__ w) {
    int idx = blockIdx.x * blockDim.x + threadIdx.x;
    if (idx >= WQ_ELEMS) return;
    int chunk = idx >> 6;            // off*4+cq
    int rem = idx & 63;
    int h = rem >> 5;
    int lane = rem & 31;
    int off = chunk >> 2, cq = chunk & 3;
    int tg = lane >> 2, tk = lane & 3;
    int k0 = off * 32 + cq * 8;
    const float s = 0.17677669529663688f;   // 1/sqrt(32)
    int oa = (2 * h) * 8 + tg;               // always < 27
    int ob = (2 * h + 1) * 8 + tg;           // may be >= 27
    float fx = w[oa * 864 + k0 + tk] * s;
    float fy = w[oa * 864 + k0 + tk + 4] * s;
    float fz = (ob < NOFF_) ? w[ob * 864 + k0 + tk] * s : 0.f;
    float fw = (ob < NOFF_) ? w[ob * 864 + k0 + tk + 4] * s : 0.f;
    uint32_t ux, uy, uz, uw;
    asm("cvt.rna.tf32.f32 %0, %1;" : "=r"(ux) : "f"(fx));
    asm("cvt.rna.tf32.f32 %0, %1;" : "=r"(uy) : "f"(fy));
    asm("cvt.rna.tf32.f32 %0, %1;" : "=r"(uz) : "f"(fz));
    asm("cvt.rna.tf32.f32 %0, %1;" : "=r"(uw) : "f"(fw));
    WQ_g[idx] = make_float4(__uint_as_float(ux), __uint_as_float(uy),
                            __uint_as_float(uz), __uint_as_float(uw));
}

// ---------------- mma helpers ----------------
__device__ __forceinline__ void mma_tf32(float* d, uint32_t a0, uint32_t a1,
                                         uint32_t a2, uint32_t a3,
                                         float b0, float b1) {
    asm volatile(
        "mma.sync.aligned.m16n8k8.row.col.f32.tf32.tf32.f32 "
        "{%0,%1,%2,%3}, {%4,%5,%6,%7}, {%8,%9}, {%0,%1,%2,%3};"
        : "+f"(d[0]), "+f"(d[1]), "+f"(d[2]), "+f"(d[3])
        : "r"(a0), "r"(a1), "r"(a2), "r"(a3),
          "r"(__float_as_uint(b0)), "r"(__float_as_uint(b1)));
}
__device__ __forceinline__ uint32_t prod_tf32(float a, float b) {
    uint32_t u;
    float p = a * b;
    asm("cvt.rna.tf32.f32 %0, %1;" : "=r"(u) : "f"(p));
    return u;
}

// ---------------- main kernel ----------------
__global__ void __launch_bounds__(256, 2)
corr_mma(const float* __restrict__ in1, const float* __restrict__ in2,
         const float* __restrict__ bias, float* __restrict__ out)
{
    extern __shared__ float4 wfs[];   // WQ image, 6912 float4

    const int tid = threadIdx.x;
    for (int i = tid; i < WQ_ELEMS; i += 256) wfs[i] = WQ_g[i];
    __syncthreads();

    const int lane = tid & 31;
    const int wid  = tid >> 5;
    const int tg = lane >> 2;     // x-group 0..7
    const int tk = lane & 3;      // k-in-group 0..3

    const int gw  = blockIdx.x * 8 + wid;   // 0..8191
    const int vbase = gw * 32;              // first voxel (32 consecutive x)
    const int xw0 = vbase & 63;             // 0 or 32
    const int z = vbase >> 12, y = (vbase >> 6) & 63;
    const int gx = xw0 + 4 * tg;            // lane's first x
    const bool lo_edge = (gx == 0);
    const bool hi_edge = (gx == 60);

    float acc0[16], acc1[16];
#pragma unroll
    for (int i = 0; i < 16; i++) { acc0[i] = 0.f; acc1[i] = 0.f; }

#pragma unroll 1
    for (int cq = 0; cq < 4; cq++) {
        const float* q = in1 + (cq * 8 + tk) * VOX + vbase + 4 * tg;
        const float4 i0 = __ldg(reinterpret_cast<const float4*>(q));
        const float4 i1 = __ldg(reinterpret_cast<const float4*>(q + 4 * VOX));

#pragma unroll 1
        for (int dz = 0; dz < 3; dz++) {
            const int zz = z + dz - 1;
#pragma unroll 1
            for (int dy = 0; dy < 3; dy++) {
                const int yy = y + dy - 1;
                const bool okzy = ((unsigned)zz < 64u) & ((unsigned)yy < 64u);

                // 6-wide x windows [gx-1, gx+4] for channels tk and tk+4
                float w0[6], w1[6];
                if (okzy) {
                    const float* p0 = in2 + (cq * 8 + tk) * VOX
                                    + (zz << 12) + (yy << 6) + gx;
                    const float* p1 = p0 + 4 * VOX;
                    const float4 v0 = __ldg(reinterpret_cast<const float4*>(p0));
                    const float4 v1 = __ldg(reinterpret_cast<const float4*>(p1));
                    w0[1] = v0.x; w0[2] = v0.y; w0[3] = v0.z; w0[4] = v0.w;
                    w1[1] = v1.x; w1[2] = v1.y; w1[3] = v1.z; w1[4] = v1.w;
                    w0[0] = lo_edge ? 0.f : __ldg(p0 - 1);
                    w1[0] = lo_edge ? 0.f : __ldg(p1 - 1);
                    w0[5] = hi_edge ? 0.f : __ldg(p0 + 4);
                    w1[5] = hi_edge ? 0.f : __ldg(p1 + 4);
                } else {
#pragma unroll
                    for (int i = 0; i < 6; i++) { w0[i] = 0.f; w1[i] = 0.f; }
                }

#pragma unroll
                for (int dx = 0; dx < 3; dx++) {
                    const int off = (dz * 3 + dy) * 3 + dx;
                    const float4* wq = wfs + (off * 4 + cq) * 64 + lane;
                    const float4 wA = wq[0];
                    const float4 wB = wq[32];

                    // mt0: rows tg,tg+8 -> x = 4tg, 4tg+1 (+dx-1)
                    {
                        const uint32_t a0 = prod_tf32(i0.x, w0[dx]);
                        const uint32_t a1 = prod_tf32(i0.y, w0[dx + 1]);
                        const uint32_t a2 = prod_tf32(i1.x, w1[dx]);
                        const uint32_t a3 = prod_tf32(i1.y, w1[dx + 1]);
                        mma_tf32(acc0 + 0,  a0, a1, a2, a3, wA.x, wA.y);
                        mma_tf32(acc0 + 4,  a0, a1, a2, a3, wA.z, wA.w);
                        mma_tf32(acc0 + 8,  a0, a1, a2, a3, wB.x, wB.y);
                        mma_tf32(acc0 + 12, a0, a1, a2, a3, wB.z, wB.w);
                    }
                    // mt1: x = 4tg+2, 4tg+3 (+dx-1)
                    {
                        const uint32_t a0 = prod_tf32(i0.z, w0[dx + 2]);
                        const uint32_t a1 = prod_tf32(i0.w, w0[dx + 3]);
                        const uint32_t a2 = prod_tf32(i1.z, w1[dx + 2]);
                        const uint32_t a3 = prod_tf32(i1.w, w1[dx + 3]);
                        mma_tf32(acc1 + 0,  a0, a1, a2, a3, wA.x, wA.y);
                        mma_tf32(acc1 + 4,  a0, a1, a2, a3, wA.z, wA.w);
                        mma_tf32(acc1 + 8,  a0, a1, a2, a3, wB.x, wB.y);
                        mma_tf32(acc1 + 12, a0, a1, a2, a3, wB.z, wB.w);
                    }
                }
            }
        }
    }

    // epilogue: output o = nt*8 + 2tk (+1); x = 4tg..4tg+3 -> one STG.128
#pragma unroll
    for (int nt = 0; nt < 4; nt++) {
        const int o0 = nt * 8 + 2 * tk;
        const int o1 = o0 + 1;
        if (o0 < NOFF_) {
            const float b = __ldg(bias + o0);
            const float4 r = make_float4(acc0[nt * 4 + 0] + b, acc0[nt * 4 + 2] + b,
                                         acc1[nt * 4 + 0] + b, acc1[nt * 4 + 2] + b);
            *reinterpret_cast<float4*>(out + o0 * VOX + vbase + 4 * tg) = r;
        }
        if (o1 < NOFF_) {
            const float b = __ldg(bias + o1);
            const float4 r = make_float4(acc0[nt * 4 + 1] + b, acc0[nt * 4 + 3] + b,
                                         acc1[nt * 4 + 1] + b, acc1[nt * 4 + 3] + b);
            *reinterpret_cast<float4*>(out + o1 * VOX + vbase + 4 * tg) = r;
        }
    }
}

extern "C" void kernel_launch(void* const* d_in, const int* in_sizes, int n_in,
                              void* d_out, int out_size) {
    const float* in1 = (const float*)d_in[0];
    const float* in2 = (const float*)d_in[1];
    const float* w   = (const float*)d_in[2];
    const float* b   = (const float*)d_in[3];
    float* out = (float*)d_out;

    stage_weights<<<(WQ_ELEMS + 255) / 256, 256>>>(w);

    const int smem = WQ_ELEMS * (int)sizeof(float4);   // 110592
    cudaFuncSetAttribute(corr_mma,
                         cudaFuncAttributeMaxDynamicSharedMemorySize, smem);
    corr_mma<<<1024, 256, smem>>>(in1, in2, b, out);
}

// round 5
// speedup vs baseline: 2.7035x; 1.0146x over previous
#include <cuda_runtime.h>
#include <cstdint>

// CorrTorch via warp-level tf32 mma.sync (m16n8k8), M=64 (full x-row) per warp:
//   out[o, v] = bias[o] + sum_{off,c} W'[o, off*32+c] * in1[c,v] * in2[c, v+off]
// Lane tg owns x = {4tg..4tg+3} (half 0) and {32+4tg..35+4tg} (half 1).
// Weight fragments loaded ONCE per (off,cq) chunk and reused for both halves,
// halving weight LDS bytes per voxel vs the 32-voxel tile.

#define C_    32
#define NOFF_ 27
#define VOX   262144                 // 64^3
#define NCHUNK 108                   // 27 offsets * 4 k8-chunks
#define WQ_ELEMS (NCHUNK * 64)       // float4 count = 6912 (110592 B)
#define TPB   192                    // 6 warps

__device__ float4 WQ_g[WQ_ELEMS];    // packed tf32 weight fragments

// ---------------- weight staging ----------------
// [(off*4+cq)*64 + h*32 + lane] -> float4
//   h=0: (nt0.b0, nt0.b1, nt1.b0, nt1.b1); h=1: (nt2..., nt3...)
//   b0 = W'[o=nt*8+tg][k0+tk], b1 = W'[o][k0+tk+4], tf32-rounded, o>=27 -> 0.
__global__ void stage_weights(const float* __restrict__ w) {
    int idx = blockIdx.x * blockDim.x + threadIdx.x;
    if (idx >= WQ_ELEMS) return;
    int chunk = idx >> 6;            // off*4+cq
    int rem = idx & 63;
    int h = rem >> 5;
    int lane = rem & 31;
    int off = chunk >> 2, cq = chunk & 3;
    int tg = lane >> 2, tk = lane & 3;
    int k0 = off * 32 + cq * 8;
    const float s = 0.17677669529663688f;   // 1/sqrt(32)
    int oa = (2 * h) * 8 + tg;
    int ob = (2 * h + 1) * 8 + tg;
    float fx = w[oa * 864 + k0 + tk] * s;
    float fy = w[oa * 864 + k0 + tk + 4] * s;
    float fz = (ob < NOFF_) ? w[ob * 864 + k0 + tk] * s : 0.f;
    float fw = (ob < NOFF_) ? w[ob * 864 + k0 + tk + 4] * s : 0.f;
    uint32_t ux, uy, uz, uw;
    asm("cvt.rna.tf32.f32 %0, %1;" : "=r"(ux) : "f"(fx));
    asm("cvt.rna.tf32.f32 %0, %1;" : "=r"(uy) : "f"(fy));
    asm("cvt.rna.tf32.f32 %0, %1;" : "=r"(uz) : "f"(fz));
    asm("cvt.rna.tf32.f32 %0, %1;" : "=r"(uw) : "f"(fw));
    WQ_g[idx] = make_float4(__uint_as_float(ux), __uint_as_float(uy),
                            __uint_as_float(uz), __uint_as_float(uw));
}

// ---------------- mma helpers ----------------
__device__ __forceinline__ void mma_tf32(float* d, uint32_t a0, uint32_t a1,
                                         uint32_t a2, uint32_t a3,
                                         float b0, float b1) {
    asm volatile(
        "mma.sync.aligned.m16n8k8.row.col.f32.tf32.tf32.f32 "
        "{%0,%1,%2,%3}, {%4,%5,%6,%7}, {%8,%9}, {%0,%1,%2,%3};"
        : "+f"(d[0]), "+f"(d[1]), "+f"(d[2]), "+f"(d[3])
        : "r"(a0), "r"(a1), "r"(a2), "r"(a3),
          "r"(__float_as_uint(b0)), "r"(__float_as_uint(b1)));
}
__device__ __forceinline__ uint32_t prod_tf32(float a, float b) {
    uint32_t u;
    float p = a * b;
    asm("cvt.rna.tf32.f32 %0, %1;" : "=r"(u) : "f"(p));
    return u;
}

// do all 8 mma for one half at one dx
__device__ __forceinline__ void half_mma(float* m0, float* m1,
                                         const float4& i0, const float4& i1,
                                         const float* w0, const float* w1,
                                         int dx,
                                         const float4& wA, const float4& wB) {
    {
        const uint32_t a0 = prod_tf32(i0.x, w0[dx]);
        const uint32_t a1 = prod_tf32(i0.y, w0[dx + 1]);
        const uint32_t a2 = prod_tf32(i1.x, w1[dx]);
        const uint32_t a3 = prod_tf32(i1.y, w1[dx + 1]);
        mma_tf32(m0 + 0,  a0, a1, a2, a3, wA.x, wA.y);
        mma_tf32(m0 + 4,  a0, a1, a2, a3, wA.z, wA.w);
        mma_tf32(m0 + 8,  a0, a1, a2, a3, wB.x, wB.y);
        mma_tf32(m0 + 12, a0, a1, a2, a3, wB.z, wB.w);
    }
    {
        const uint32_t a0 = prod_tf32(i0.z, w0[dx + 2]);
        const uint32_t a1 = prod_tf32(i0.w, w0[dx + 3]);
        const uint32_t a2 = prod_tf32(i1.z, w1[dx + 2]);
        const uint32_t a3 = prod_tf32(i1.w, w1[dx + 3]);
        mma_tf32(m1 + 0,  a0, a1, a2, a3, wA.x, wA.y);
        mma_tf32(m1 + 4,  a0, a1, a2, a3, wA.z, wA.w);
        mma_tf32(m1 + 8,  a0, a1, a2, a3, wB.x, wB.y);
        mma_tf32(m1 + 12, a0, a1, a2, a3, wB.z, wB.w);
    }
}

// ---------------- main kernel ----------------
__global__ void __launch_bounds__(TPB, 2)
corr_mma(const float* __restrict__ in1, const float* __restrict__ in2,
         const float* __restrict__ bias, float* __restrict__ out)
{
    extern __shared__ float4 wfs[];   // WQ image, 6912 float4

    const int tid = threadIdx.x;
    for (int i = tid; i < WQ_ELEMS; i += TPB) wfs[i] = WQ_g[i];
    __syncthreads();

    const int lane = tid & 31;
    const int wid  = tid >> 5;
    const int tg = lane >> 2;     // x-group 0..7
    const int tk = lane & 3;      // k-in-group 0..3

    const int gw = blockIdx.x * (TPB / 32) + wid;   // row id 0..4095
    if (gw >= 4096) return;
    const int vbase = gw << 6;              // full x-row: 64 voxels
    const int z = gw >> 6, y = gw & 63;
    const int x4 = 4 * tg;

    // acc[half][mt]: 4 nt-tiles x 4 regs
    float aA0[16], aA1[16], aB0[16], aB1[16];
#pragma unroll
    for (int i = 0; i < 16; i++) { aA0[i]=0.f; aA1[i]=0.f; aB0[i]=0.f; aB1[i]=0.f; }

#pragma unroll 1
    for (int cq = 0; cq < 4; cq++) {
        const float* q = in1 + (cq * 8 + tk) * VOX + vbase + x4;
        const float4 i0a = __ldg(reinterpret_cast<const float4*>(q));
        const float4 i1a = __ldg(reinterpret_cast<const float4*>(q + 4 * VOX));
        const float4 i0b = __ldg(reinterpret_cast<const float4*>(q + 32));
        const float4 i1b = __ldg(reinterpret_cast<const float4*>(q + 4 * VOX + 32));

#pragma unroll 1
        for (int dz = 0; dz < 3; dz++) {
            const int zz = z + dz - 1;
#pragma unroll 1
            for (int dy = 0; dy < 3; dy++) {
                const int yy = y + dy - 1;
                const bool okzy = ((unsigned)zz < 64u) & ((unsigned)yy < 64u);

                // windows [x-1 .. x+4] per channel per half
                float w0a[6], w1a[6], w0b[6], w1b[6];
                if (okzy) {
                    const float* r0 = in2 + (cq * 8 + tk) * VOX
                                    + (zz << 12) + (yy << 6);
                    const float* r1 = r0 + 4 * VOX;
                    const float4 va0 = __ldg(reinterpret_cast<const float4*>(r0 + x4));
                    const float4 va1 = __ldg(reinterpret_cast<const float4*>(r1 + x4));
                    const float4 vb0 = __ldg(reinterpret_cast<const float4*>(r0 + 32 + x4));
                    const float4 vb1 = __ldg(reinterpret_cast<const float4*>(r1 + 32 + x4));
                    w0a[1]=va0.x; w0a[2]=va0.y; w0a[3]=va0.z; w0a[4]=va0.w;
                    w1a[1]=va1.x; w1a[2]=va1.y; w1a[3]=va1.z; w1a[4]=va1.w;
                    w0b[1]=vb0.x; w0b[2]=vb0.y; w0b[3]=vb0.z; w0b[4]=vb0.w;
                    w1b[1]=vb1.x; w1b[2]=vb1.y; w1b[3]=vb1.z; w1b[4]=vb1.w;
                    // halos: half0 lo is pad only at tg==0; half1 hi pad at tg==7
                    w0a[0] = (tg > 0) ? __ldg(r0 + x4 - 1) : 0.f;
                    w1a[0] = (tg > 0) ? __ldg(r1 + x4 - 1) : 0.f;
                    w0a[5] = __ldg(r0 + x4 + 4);        // x<=36, always valid
                    w1a[5] = __ldg(r1 + x4 + 4);
                    w0b[0] = __ldg(r0 + 31 + x4);       // x>=31, always valid
                    w1b[0] = __ldg(r1 + 31 + x4);
                    w0b[5] = (tg < 7) ? __ldg(r0 + 36 + x4) : 0.f;
                    w1b[5] = (tg < 7) ? __ldg(r1 + 36 + x4) : 0.f;
                } else {
#pragma unroll
                    for (int i = 0; i < 6; i++) {
                        w0a[i]=0.f; w1a[i]=0.f; w0b[i]=0.f; w1b[i]=0.f;
                    }
                }

#pragma unroll
                for (int dx = 0; dx < 3; dx++) {
                    const int off = (dz * 3 + dy) * 3 + dx;
                    const float4* wq = wfs + (off * 4 + cq) * 64 + lane;
                    const float4 wA = wq[0];
                    const float4 wB = wq[32];
                    half_mma(aA0, aA1, i0a, i1a, w0a, w1a, dx, wA, wB);
                    half_mma(aB0, aB1, i0b, i1b, w0b, w1b, dx, wA, wB);
                }
            }
        }
    }

    // epilogue: output o = nt*8 + 2tk (+1); x-consecutive -> STG.128
#pragma unroll
    for (int nt = 0; nt < 4; nt++) {
        const int o0 = nt * 8 + 2 * tk;
        const int o1 = o0 + 1;
        if (o0 < NOFF_) {
            const float b = __ldg(bias + o0);
            float4 r0 = make_float4(aA0[nt*4+0]+b, aA0[nt*4+2]+b,
                                    aA1[nt*4+0]+b, aA1[nt*4+2]+b);
            float4 r1 = make_float4(aB0[nt*4+0]+b, aB0[nt*4+2]+b,
                                    aB1[nt*4+0]+b, aB1[nt*4+2]+b);
            *reinterpret_cast<float4*>(out + o0 * VOX + vbase + x4)      = r0;
            *reinterpret_cast<float4*>(out + o0 * VOX + vbase + 32 + x4) = r1;
        }
        if (o1 < NOFF_) {
            const float b = __ldg(bias + o1);
            float4 r0 = make_float4(aA0[nt*4+1]+b, aA0[nt*4+3]+b,
                                    aA1[nt*4+1]+b, aA1[nt*4+3]+b);
            float4 r1 = make_float4(aB0[nt*4+1]+b, aB0[nt*4+3]+b,
                                    aB1[nt*4+1]+b, aB1[nt*4+3]+b);
            *reinterpret_cast<float4*>(out + o1 * VOX + vbase + x4)      = r0;
            *reinterpret_cast<float4*>(out + o1 * VOX + vbase + 32 + x4) = r1;
        }
    }
}

extern "C" void kernel_launch(void* const* d_in, const int* in_sizes, int n_in,
                              void* d_out, int out_size) {
    const float* in1 = (const float*)d_in[0];
    const float* in2 = (const float*)d_in[1];
    const float* w   = (const float*)d_in[2];
    const float* b   = (const float*)d_in[3];
    float* out = (float*)d_out;

    stage_weights<<<(WQ_ELEMS + 255) / 256, 256>>>(w);

    const int smem = WQ_ELEMS * (int)sizeof(float4);   // 110592
    cudaFuncSetAttribute(corr_mma,
                         cudaFuncAttributeMaxDynamicSharedMemorySize, smem);
    const int nwarps = 4096;
    const int wpb = TPB / 32;
    corr_mma<<<(nwarps + wpb - 1) / wpb, TPB, smem>>>(in1, in2, b, out);
}

// round 6
// speedup vs baseline: 3.0552x; 1.1301x over previous
#include <cuda_runtime.h>
#include <cuda_fp16.h>
#include <cstdint>

// CorrTorch via warp-level fp16 mma.sync (m16n8k16), x-consecutive lanes:
//   out[o, v] = bias[o] + sum_{off,c} W'[o, off*32+c] * in1[c,v] * in2[c, v+off]
// Per warp: 32 consecutive-x voxels x 32 outputs (o padded 27->32).
// A = fp32 products rounded once to fp16 (same 11-bit mantissa as tf32),
// B = fp16 weight fragments pre-packed in SMEM. K chunked 32 = 2 x k16.

#define C_    32
#define NOFF_ 27
#define VOX   262144                  // 64^3
#define NCHUNK 54                     // 27 offsets * 2 k16-chunks
#define WQ_ELEMS (NCHUNK * 64)        // uint4 count = 3456 (55296 B)
#define TPB   256

__device__ uint4 WQ_g[WQ_ELEMS];      // packed fp16 weight fragments

__device__ __forceinline__ uint32_t f2h2(float lo, float hi) {
    uint32_t r;
    asm("cvt.rn.f16x2.f32 %0, %1, %2;" : "=r"(r) : "f"(hi), "f"(lo));
    return r;
}

// ---------------- weight staging ----------------
// [(chunk)*64 + h*32 + lane] -> uint4 (nt=2h: b0,b1 ; nt=2h+1: b0,b1)
//   b0 = h2(W'[o][k0+2tk], W'[o][k0+2tk+1]); b1 = same at +8. o = nt*8+tg.
__global__ void stage_weights(const float* __restrict__ w) {
    int idx = blockIdx.x * blockDim.x + threadIdx.x;
    if (idx >= WQ_ELEMS) return;
    int chunk = idx >> 6;            // off*2 + kc
    int rem = idx & 63;
    int h = rem >> 5;
    int lane = rem & 31;
    int off = chunk >> 1, kc = chunk & 1;
    int tg = lane >> 2, tk = lane & 3;
    int k0 = off * 32 + kc * 16;
    const float s = 0.17677669529663688f;   // 1/sqrt(32)
    int oa = (2 * h) * 8 + tg;               // < 27 always
    int ob = (2 * h + 1) * 8 + tg;           // may be >= 27
    uint4 r;
    r.x = f2h2(w[oa * 864 + k0 + 2 * tk] * s,     w[oa * 864 + k0 + 2 * tk + 1] * s);
    r.y = f2h2(w[oa * 864 + k0 + 2 * tk + 8] * s, w[oa * 864 + k0 + 2 * tk + 9] * s);
    r.z = (ob < NOFF_) ? f2h2(w[ob * 864 + k0 + 2 * tk] * s,
                              w[ob * 864 + k0 + 2 * tk + 1] * s) : 0u;
    r.w = (ob < NOFF_) ? f2h2(w[ob * 864 + k0 + 2 * tk + 8] * s,
                              w[ob * 864 + k0 + 2 * tk + 9] * s) : 0u;
    WQ_g[idx] = r;
}

// ---------------- mma helper ----------------
__device__ __forceinline__ void mma16816(float* d, uint32_t a0, uint32_t a1,
                                         uint32_t a2, uint32_t a3,
                                         uint32_t b0, uint32_t b1) {
    asm volatile(
        "mma.sync.aligned.m16n8k16.row.col.f32.f16.f16.f32 "
        "{%0,%1,%2,%3}, {%4,%5,%6,%7}, {%8,%9}, {%0,%1,%2,%3};"
        : "+f"(d[0]), "+f"(d[1]), "+f"(d[2]), "+f"(d[3])
        : "r"(a0), "r"(a1), "r"(a2), "r"(a3), "r"(b0), "r"(b1));
}

// ---------------- main kernel ----------------
__global__ void __launch_bounds__(TPB, 2)
corr_mma(const float* __restrict__ in1, const float* __restrict__ in2,
         const float* __restrict__ bias, float* __restrict__ out)
{
    extern __shared__ uint4 wfs[];   // 3456 uint4

    const int tid = threadIdx.x;
    for (int i = tid; i < WQ_ELEMS; i += TPB) wfs[i] = WQ_g[i];
    __syncthreads();

    const int lane = tid & 31;
    const int wid  = tid >> 5;
    const int tg = lane >> 2;     // x-group 0..7
    const int tk = lane & 3;      // k-in-group 0..3

    const int gw = blockIdx.x * 8 + wid;    // 0..8191
    const int vbase = gw * 32;              // 32 consecutive-x voxels
    const int xw0 = vbase & 63;             // 0 or 32
    const int z = vbase >> 12, y = (vbase >> 6) & 63;
    const int gx = xw0 + 4 * tg;            // lane's first x
    const bool lo_edge = (gx == 0);
    const bool hi_edge = (gx == 60);

    // acc[mt][nt*4 + i]
    float acc0[16], acc1[16];
#pragma unroll
    for (int i = 0; i < 16; i++) { acc0[i] = 0.f; acc1[i] = 0.f; }

#pragma unroll 1
    for (int kc = 0; kc < 2; kc++) {
        // 4 channels this thread touches in this k16 chunk
        const int c0 = kc * 16;
        int ch[4];
        ch[0] = c0 + 2 * tk;     ch[1] = ch[0] + 1;
        ch[2] = c0 + 2 * tk + 8; ch[3] = ch[2] + 1;

        float i1v[4][4];
#pragma unroll
        for (int j = 0; j < 4; j++) {
            const float4 v = __ldg(reinterpret_cast<const float4*>(
                in1 + ch[j] * VOX + vbase + 4 * tg));
            i1v[j][0] = v.x; i1v[j][1] = v.y; i1v[j][2] = v.z; i1v[j][3] = v.w;
        }

#pragma unroll 1
        for (int dz = 0; dz < 3; dz++) {
            const int zz = z + dz - 1;
#pragma unroll 1
            for (int dy = 0; dy < 3; dy++) {
                const int yy = y + dy - 1;
                const bool okzy = ((unsigned)zz < 64u) & ((unsigned)yy < 64u);

                float wv[4][6];   // x windows [gx-1 .. gx+4] per channel
                if (okzy) {
                    const float* base = in2 + (zz << 12) + (yy << 6) + gx;
#pragma unroll
                    for (int j = 0; j < 4; j++) {
                        const float* p = base + ch[j] * VOX;
                        const float4 v = __ldg(reinterpret_cast<const float4*>(p));
                        wv[j][1] = v.x; wv[j][2] = v.y; wv[j][3] = v.z; wv[j][4] = v.w;
                        wv[j][0] = lo_edge ? 0.f : __ldg(p - 1);
                        wv[j][5] = hi_edge ? 0.f : __ldg(p + 4);
                    }
                } else {
#pragma unroll
                    for (int j = 0; j < 4; j++)
#pragma unroll
                        for (int i = 0; i < 6; i++) wv[j][i] = 0.f;
                }

#pragma unroll
                for (int dx = 0; dx < 3; dx++) {
                    const int off = (dz * 3 + dy) * 3 + dx;
                    const int chunk = off * 2 + kc;
                    const uint4 wA = wfs[chunk * 64 + lane];
                    const uint4 wB = wfs[chunk * 64 + 32 + lane];

#pragma unroll
                    for (int mt = 0; mt < 2; mt++) {
                        const int p0 = 2 * mt, p1 = 2 * mt + 1;
                        // a0: row tg (x=4tg+p0), channels ch0,ch1 (k=2tk,2tk+1)
                        const uint32_t a0 = f2h2(i1v[0][p0] * wv[0][dx + p0],
                                                 i1v[1][p0] * wv[1][dx + p0]);
                        // a1: row tg+8 (x=4tg+p1)
                        const uint32_t a1 = f2h2(i1v[0][p1] * wv[0][dx + p1],
                                                 i1v[1][p1] * wv[1][dx + p1]);
                        // a2/a3: channels ch2,ch3 (k=2tk+8,2tk+9)
                        const uint32_t a2 = f2h2(i1v[2][p0] * wv[2][dx + p0],
                                                 i1v[3][p0] * wv[3][dx + p0]);
                        const uint32_t a3 = f2h2(i1v[2][p1] * wv[2][dx + p1],
                                                 i1v[3][p1] * wv[3][dx + p1]);
                        float* acc = mt ? acc1 : acc0;
                        mma16816(acc + 0,  a0, a1, a2, a3, wA.x, wA.y);
                        mma16816(acc + 4,  a0, a1, a2, a3, wA.z, wA.w);
                        mma16816(acc + 8,  a0, a1, a2, a3, wB.x, wB.y);
                        mma16816(acc + 12, a0, a1, a2, a3, wB.z, wB.w);
                    }
                }
            }
        }
    }

    // epilogue: o = nt*8 + 2tk (+1); x = 4tg..4tg+3 -> one STG.128 per o
    // D rows: mt0 c0/c1 -> x=4tg, c2/c3 -> 4tg+1; mt1 -> 4tg+2, 4tg+3
#pragma unroll
    for (int nt = 0; nt < 4; nt++) {
        const int o0 = nt * 8 + 2 * tk;
        const int o1 = o0 + 1;
        if (o0 < NOFF_) {
            const float b = __ldg(bias + o0);
            const float4 r = make_float4(acc0[nt * 4 + 0] + b, acc0[nt * 4 + 2] + b,
                                         acc1[nt * 4 + 0] + b, acc1[nt * 4 + 2] + b);
            *reinterpret_cast<float4*>(out + o0 * VOX + vbase + 4 * tg) = r;
        }
        if (o1 < NOFF_) {
            const float b = __ldg(bias + o1);
            const float4 r = make_float4(acc0[nt * 4 + 1] + b, acc0[nt * 4 + 3] + b,
                                         acc1[nt * 4 + 1] + b, acc1[nt * 4 + 3] + b);
            *reinterpret_cast<float4*>(out + o1 * VOX + vbase + 4 * tg) = r;
        }
    }
}

extern "C" void kernel_launch(void* const* d_in, const int* in_sizes, int n_in,
                              void* d_out, int out_size) {
    const float* in1 = (const float*)d_in[0];
    const float* in2 = (const float*)d_in[1];
    const float* w   = (const float*)d_in[2];
    const float* b   = (const float*)d_in[3];
    float* out = (float*)d_out;

    stage_weights<<<(WQ_ELEMS + 255) / 256, 256>>>(w);

    const int smem = WQ_ELEMS * (int)sizeof(uint4);   // 55296
    cudaFuncSetAttribute(corr_mma,
                         cudaFuncAttributeMaxDynamicSharedMemorySize, smem);
    corr_mma<<<1024, TPB, smem>>>(in1, in2, b, out);
}

// round 7
// speedup vs baseline: 3.2703x; 1.0704x over previous
#include <cuda_runtime.h>
#include <cuda_fp16.h>
#include <cstdint>

// CorrTorch via warp-level fp16 mma.sync (m16n8k16), x-consecutive lanes:
//   out[o, v] = bias[o] + sum_{off,c} W'[o, off*32+c] * in1[c,v] * in2[c, v+off]
// Per warp: 32 consecutive-x voxels x 32 outputs (o padded 27->32).
// R7: shuffle-based x-halos (1 broadcast edge load per channel instead of 2
// scalar loads) + depth-2 software pipeline over the 9 (dz,dy) iterations.

#define C_    32
#define NOFF_ 27
#define VOX   262144                  // 64^3
#define NCHUNK 54                     // 27 offsets * 2 k16-chunks
#define WQ_ELEMS (NCHUNK * 64)        // uint4 count = 3456 (55296 B)
#define TPB   256

__device__ uint4 WQ_g[WQ_ELEMS];      // packed fp16 weight fragments

__device__ __forceinline__ uint32_t f2h2(float lo, float hi) {
    uint32_t r;
    asm("cvt.rn.f16x2.f32 %0, %1, %2;" : "=r"(r) : "f"(hi), "f"(lo));
    return r;
}

// ---------------- weight staging (same layout as R6) ----------------
__global__ void stage_weights(const float* __restrict__ w) {
    int idx = blockIdx.x * blockDim.x + threadIdx.x;
    if (idx >= WQ_ELEMS) return;
    int chunk = idx >> 6;            // off*2 + kc
    int rem = idx & 63;
    int h = rem >> 5;
    int lane = rem & 31;
    int off = chunk >> 1, kc = chunk & 1;
    int tg = lane >> 2, tk = lane & 3;
    int k0 = off * 32 + kc * 16;
    const float s = 0.17677669529663688f;   // 1/sqrt(32)
    int oa = (2 * h) * 8 + tg;
    int ob = (2 * h + 1) * 8 + tg;
    uint4 r;
    r.x = f2h2(w[oa * 864 + k0 + 2 * tk] * s,     w[oa * 864 + k0 + 2 * tk + 1] * s);
    r.y = f2h2(w[oa * 864 + k0 + 2 * tk + 8] * s, w[oa * 864 + k0 + 2 * tk + 9] * s);
    r.z = (ob < NOFF_) ? f2h2(w[ob * 864 + k0 + 2 * tk] * s,
                              w[ob * 864 + k0 + 2 * tk + 1] * s) : 0u;
    r.w = (ob < NOFF_) ? f2h2(w[ob * 864 + k0 + 2 * tk + 8] * s,
                              w[ob * 864 + k0 + 2 * tk + 9] * s) : 0u;
    WQ_g[idx] = r;
}

// ---------------- mma helper ----------------
__device__ __forceinline__ void mma16816(float* d, uint32_t a0, uint32_t a1,
                                         uint32_t a2, uint32_t a3,
                                         uint32_t b0, uint32_t b1) {
    asm volatile(
        "mma.sync.aligned.m16n8k16.row.col.f32.f16.f16.f32 "
        "{%0,%1,%2,%3}, {%4,%5,%6,%7}, {%8,%9}, {%0,%1,%2,%3};"
        : "+f"(d[0]), "+f"(d[1]), "+f"(d[2]), "+f"(d[3])
        : "r"(a0), "r"(a1), "r"(a2), "r"(a3), "r"(b0), "r"(b1));
}

// ---------------- main kernel ----------------
__global__ void __launch_bounds__(TPB, 2)
corr_mma(const float* __restrict__ in1, const float* __restrict__ in2,
         const float* __restrict__ bias, float* __restrict__ out)
{
    extern __shared__ uint4 wfs[];   // 3456 uint4

    const int tid = threadIdx.x;
    for (int i = tid; i < WQ_ELEMS; i += TPB) wfs[i] = WQ_g[i];
    __syncthreads();

    const int lane = tid & 31;
    const int wid  = tid >> 5;
    const int tg = lane >> 2;     // x-group 0..7
    const int tk = lane & 3;      // k-in-group 0..3

    const int gw = blockIdx.x * 8 + wid;    // 0..8191
    const int vbase = gw * 32;              // 32 consecutive-x voxels
    const int xw0 = vbase & 63;             // 0 or 32
    const int z = vbase >> 12, y = (vbase >> 6) & 63;
    const int gx = xw0 + 4 * tg;            // lane's first x
    const bool lo_real = (xw0 == 32);       // true: lo halo is memory, hi is pad
    const int  ex = lo_real ? 31 : 32;      // the one real edge x in this row

    float acc0[16], acc1[16];
#pragma unroll
    for (int i = 0; i < 16; i++) { acc0[i] = 0.f; acc1[i] = 0.f; }

#pragma unroll 1
    for (int kc = 0; kc < 2; kc++) {
        const int c0 = kc * 16;
        int ch[4];
        ch[0] = c0 + 2 * tk;     ch[1] = ch[0] + 1;
        ch[2] = c0 + 2 * tk + 8; ch[3] = ch[2] + 1;

        float i1v[4][4];
#pragma unroll
        for (int j = 0; j < 4; j++) {
            const float4 v = __ldg(reinterpret_cast<const float4*>(
                in1 + ch[j] * VOX + vbase + 4 * tg));
            i1v[j][0] = v.x; i1v[j][1] = v.y; i1v[j][2] = v.z; i1v[j][3] = v.w;
        }

        // ---- depth-2 pipeline over 9 (dz,dy) iterations ----
        float4 v[4]; float e[4];
        float4 vn[4]; float en[4];

        // prologue: load iter 0
        {
            const int zz = z - 1, yy = y - 1;
            const bool ok = ((unsigned)zz < 64u) & ((unsigned)yy < 64u);
            const float* row = in2 + (zz << 12) + (yy << 6);
#pragma unroll
            for (int j = 0; j < 4; j++) {
                v[j] = ok ? __ldg(reinterpret_cast<const float4*>(row + ch[j] * VOX + gx))
                          : make_float4(0.f, 0.f, 0.f, 0.f);
                e[j] = ok ? __ldg(row + ch[j] * VOX + ex) : 0.f;
            }
        }

#pragma unroll 1
        for (int it = 0; it < 9; it++) {
            // prefetch next iteration
            if (it < 8) {
                const int nit = it + 1;
                const int ndz = nit / 3, ndy = nit % 3;
                const int zz = z + ndz - 1, yy = y + ndy - 1;
                const bool ok = ((unsigned)zz < 64u) & ((unsigned)yy < 64u);
                const float* row = in2 + (zz << 12) + (yy << 6);
#pragma unroll
                for (int j = 0; j < 4; j++) {
                    vn[j] = ok ? __ldg(reinterpret_cast<const float4*>(row + ch[j] * VOX + gx))
                               : make_float4(0.f, 0.f, 0.f, 0.f);
                    en[j] = ok ? __ldg(row + ch[j] * VOX + ex) : 0.f;
                }
            }

            // build 6-wide windows via shuffle
            float wv[4][6];
#pragma unroll
            for (int j = 0; j < 4; j++) {
                wv[j][1] = v[j].x; wv[j][2] = v[j].y;
                wv[j][3] = v[j].z; wv[j][4] = v[j].w;
                const float up = __shfl_up_sync(0xffffffffu, v[j].w, 4);
                const float dn = __shfl_down_sync(0xffffffffu, v[j].x, 4);
                wv[j][0] = (tg == 0) ? (lo_real ? e[j] : 0.f) : up;
                wv[j][5] = (tg == 7) ? (lo_real ? 0.f : e[j]) : dn;
            }

            // 3 dx offsets x 8 mma
#pragma unroll
            for (int dx = 0; dx < 3; dx++) {
                const int off = it * 3 + dx;          // (dz*3+dy)*3+dx
                const int chunk = off * 2 + kc;
                const uint4 wA = wfs[chunk * 64 + lane];
                const uint4 wB = wfs[chunk * 64 + 32 + lane];

#pragma unroll
                for (int mt = 0; mt < 2; mt++) {
                    const int p0 = 2 * mt, p1 = 2 * mt + 1;
                    const uint32_t a0 = f2h2(i1v[0][p0] * wv[0][dx + p0],
                                             i1v[1][p0] * wv[1][dx + p0]);
                    const uint32_t a1 = f2h2(i1v[0][p1] * wv[0][dx + p1],
                                             i1v[1][p1] * wv[1][dx + p1]);
                    const uint32_t a2 = f2h2(i1v[2][p0] * wv[2][dx + p0],
                                             i1v[3][p0] * wv[3][dx + p0]);
                    const uint32_t a3 = f2h2(i1v[2][p1] * wv[2][dx + p1],
                                             i1v[3][p1] * wv[3][dx + p1]);
                    float* acc = mt ? acc1 : acc0;
                    mma16816(acc + 0,  a0, a1, a2, a3, wA.x, wA.y);
                    mma16816(acc + 4,  a0, a1, a2, a3, wA.z, wA.w);
                    mma16816(acc + 8,  a0, a1, a2, a3, wB.x, wB.y);
                    mma16816(acc + 12, a0, a1, a2, a3, wB.z, wB.w);
                }
            }

            // rotate pipeline
#pragma unroll
            for (int j = 0; j < 4; j++) { v[j] = vn[j]; e[j] = en[j]; }
        }
    }

    // epilogue: o = nt*8 + 2tk (+1); x = 4tg..4tg+3 -> one STG.128 per o
#pragma unroll
    for (int nt = 0; nt < 4; nt++) {
        const int o0 = nt * 8 + 2 * tk;
        const int o1 = o0 + 1;
        if (o0 < NOFF_) {
            const float b = __ldg(bias + o0);
            const float4 r = make_float4(acc0[nt * 4 + 0] + b, acc0[nt * 4 + 2] + b,
                                         acc1[nt * 4 + 0] + b, acc1[nt * 4 + 2] + b);
            *reinterpret_cast<float4*>(out + o0 * VOX + vbase + 4 * tg) = r;
        }
        if (o1 < NOFF_) {
            const float b = __ldg(bias + o1);
            const float4 r = make_float4(acc0[nt * 4 + 1] + b, acc0[nt * 4 + 3] + b,
                                         acc1[nt * 4 + 1] + b, acc1[nt * 4 + 3] + b);
            *reinterpret_cast<float4*>(out + o1 * VOX + vbase + 4 * tg) = r;
        }
    }
}

extern "C" void kernel_launch(void* const* d_in, const int* in_sizes, int n_in,
                              void* d_out, int out_size) {
    const float* in1 = (const float*)d_in[0];
    const float* in2 = (const float*)d_in[1];
    const float* w   = (const float*)d_in[2];
    const float* b   = (const float*)d_in[3];
    float* out = (float*)d_out;

    stage_weights<<<(WQ_ELEMS + 255) / 256, 256>>>(w);

    const int smem = WQ_ELEMS * (int)sizeof(uint4);   // 55296
    cudaFuncSetAttribute(corr_mma,
                         cudaFuncAttributeMaxDynamicSharedMemorySize, smem);
    corr_mma<<<1024, TPB, smem>>>(in1, in2, b, out);
}

// round 8
// speedup vs baseline: 4.0157x; 1.2279x over previous
#include <cuda_runtime.h>
#include <cuda_fp16.h>
#include <cstdint>

// CorrTorch via warp-level fp16 mma.sync (m16n8k16), x-consecutive lanes.
// R8: in1/in2 pre-converted to fp16 channel-pair-interleaved scratch
// (half2 {ch_even, ch_odd} per voxel) -> A-fragments built with one HMUL2
// each, in2 LDG bytes halved. Weights pre-packed fp16 in SMEM (as R6/R7).

#define C_    32
#define NOFF_ 27
#define VOX   262144                  // 64^3
#define PAIRS 16                      // channel pairs
#define NCHUNK 54                     // 27 offsets * 2 k16-chunks
#define WQ_ELEMS (NCHUNK * 64)        // uint4 count = 3456 (55296 B)
#define TPB   256

__device__ uint4 WQ_g[WQ_ELEMS];            // packed fp16 weight fragments
__device__ uint32_t IN1H[PAIRS * VOX];      // half2 per voxel (16 MB)
__device__ uint32_t IN2H[PAIRS * VOX];      // half2 per voxel (16 MB)

__device__ __forceinline__ uint32_t f2h2(float lo, float hi) {
    uint32_t r;
    asm("cvt.rn.f16x2.f32 %0, %1, %2;" : "=r"(r) : "f"(hi), "f"(lo));
    return r;
}
__device__ __forceinline__ uint32_t hmul2(uint32_t a, uint32_t b) {
    uint32_t d;
    asm("mul.rn.f16x2 %0, %1, %2;" : "=r"(d) : "r"(a), "r"(b));
    return d;
}

// ---------------- input conversion prepass ----------------
__global__ void convert_inputs(const float* __restrict__ in1,
                               const float* __restrict__ in2) {
    const int idx = blockIdx.x * 256 + threadIdx.x;
    const int per_arr = PAIRS * VOX / 4;           // 1M
    if (idx >= 2 * per_arr) return;
    const int arr = (idx >= per_arr);
    const int r = idx - arr * per_arr;
    const int c2 = r / (VOX / 4);
    const int v4 = (r - c2 * (VOX / 4)) * 4;
    const float* src = arr ? in2 : in1;
    uint32_t* dst = arr ? IN2H : IN1H;
    const float4 a = __ldg(reinterpret_cast<const float4*>(src + (2 * c2) * VOX + v4));
    const float4 b = __ldg(reinterpret_cast<const float4*>(src + (2 * c2 + 1) * VOX + v4));
    uint4 o;
    o.x = f2h2(a.x, b.x); o.y = f2h2(a.y, b.y);
    o.z = f2h2(a.z, b.z); o.w = f2h2(a.w, b.w);
    *reinterpret_cast<uint4*>(dst + c2 * VOX + v4) = o;
}

// ---------------- weight staging (same layout as R6/R7) ----------------
__global__ void stage_weights(const float* __restrict__ w) {
    int idx = blockIdx.x * blockDim.x + threadIdx.x;
    if (idx >= WQ_ELEMS) return;
    int chunk = idx >> 6;            // off*2 + kc
    int rem = idx & 63;
    int h = rem >> 5;
    int lane = rem & 31;
    int off = chunk >> 1, kc = chunk & 1;
    int tg = lane >> 2, tk = lane & 3;
    int k0 = off * 32 + kc * 16;
    const float s = 0.17677669529663688f;   // 1/sqrt(32)
    int oa = (2 * h) * 8 + tg;
    int ob = (2 * h + 1) * 8 + tg;
    uint4 r;
    r.x = f2h2(w[oa * 864 + k0 + 2 * tk] * s,     w[oa * 864 + k0 + 2 * tk + 1] * s);
    r.y = f2h2(w[oa * 864 + k0 + 2 * tk + 8] * s, w[oa * 864 + k0 + 2 * tk + 9] * s);
    r.z = (ob < NOFF_) ? f2h2(w[ob * 864 + k0 + 2 * tk] * s,
                              w[ob * 864 + k0 + 2 * tk + 1] * s) : 0u;
    r.w = (ob < NOFF_) ? f2h2(w[ob * 864 + k0 + 2 * tk + 8] * s,
                              w[ob * 864 + k0 + 2 * tk + 9] * s) : 0u;
    WQ_g[idx] = r;
}

// ---------------- mma helper ----------------
__device__ __forceinline__ void mma16816(float* d, uint32_t a0, uint32_t a1,
                                         uint32_t a2, uint32_t a3,
                                         uint32_t b0, uint32_t b1) {
    asm volatile(
        "mma.sync.aligned.m16n8k16.row.col.f32.f16.f16.f32 "
        "{%0,%1,%2,%3}, {%4,%5,%6,%7}, {%8,%9}, {%0,%1,%2,%3};"
        : "+f"(d[0]), "+f"(d[1]), "+f"(d[2]), "+f"(d[3])
        : "r"(a0), "r"(a1), "r"(a2), "r"(a3), "r"(b0), "r"(b1));
}

// ---------------- main kernel ----------------
__global__ void __launch_bounds__(TPB, 2)
corr_mma(const float* __restrict__ bias, float* __restrict__ out)
{
    extern __shared__ uint4 wfs[];   // 3456 uint4

    const int tid = threadIdx.x;
    for (int i = tid; i < WQ_ELEMS; i += TPB) wfs[i] = WQ_g[i];
    __syncthreads();

    const int lane = tid & 31;
    const int wid  = tid >> 5;
    const int tg = lane >> 2;     // x-group 0..7
    const int tk = lane & 3;      // k-in-group 0..3

    const int gw = blockIdx.x * 8 + wid;    // 0..8191
    const int vbase = gw * 32;              // 32 consecutive-x voxels
    const int xw0 = vbase & 63;             // 0 or 32
    const int z = vbase >> 12, y = (vbase >> 6) & 63;
    const int gx = xw0 + 4 * tg;            // lane's first x
    const bool lo_real = (xw0 == 32);       // lo halo from memory; else hi
    const int  ex = lo_real ? 31 : 32;      // the one real edge x

    float acc0[16], acc1[16];
#pragma unroll
    for (int i = 0; i < 16; i++) { acc0[i] = 0.f; acc1[i] = 0.f; }

#pragma unroll 1
    for (int kc = 0; kc < 2; kc++) {
        // channel-pair slots: j=0 -> k = 2tk,2tk+1; j=1 -> k = 2tk+8,2tk+9
        const int c2a = kc * 8 + tk;
        const int c2b = c2a + 4;

        // in1 fragments: 4 half2 per slot (x = 4tg..4tg+3)
        const uint4 i1a = *reinterpret_cast<const uint4*>(IN1H + c2a * VOX + vbase + 4 * tg);
        const uint4 i1b = *reinterpret_cast<const uint4*>(IN1H + c2b * VOX + vbase + 4 * tg);
        uint32_t i1A[4] = {i1a.x, i1a.y, i1a.z, i1a.w};
        uint32_t i1B[4] = {i1b.x, i1b.y, i1b.z, i1b.w};

        // ---- depth-2 pipeline over 9 (dz,dy) iterations ----
        uint4 v[2]; uint32_t e[2];
        uint4 vn[2]; uint32_t en[2];
        {
            const int zz = z - 1, yy = y - 1;
            const bool ok = ((unsigned)zz < 64u) & ((unsigned)yy < 64u);
            const int rb = (zz << 12) + (yy << 6);
            const uint4 zer = make_uint4(0u, 0u, 0u, 0u);
            v[0] = ok ? *reinterpret_cast<const uint4*>(IN2H + c2a * VOX + rb + gx) : zer;
            v[1] = ok ? *reinterpret_cast<const uint4*>(IN2H + c2b * VOX + rb + gx) : zer;
            e[0] = ok ? IN2H[c2a * VOX + rb + ex] : 0u;
            e[1] = ok ? IN2H[c2b * VOX + rb + ex] : 0u;
        }

#pragma unroll 1
        for (int it = 0; it < 9; it++) {
            if (it < 8) {
                const int nit = it + 1;
                const int zz = z + nit / 3 - 1, yy = y + nit % 3 - 1;
                const bool ok = ((unsigned)zz < 64u) & ((unsigned)yy < 64u);
                const int rb = (zz << 12) + (yy << 6);
                const uint4 zer = make_uint4(0u, 0u, 0u, 0u);
                vn[0] = ok ? *reinterpret_cast<const uint4*>(IN2H + c2a * VOX + rb + gx) : zer;
                vn[1] = ok ? *reinterpret_cast<const uint4*>(IN2H + c2b * VOX + rb + gx) : zer;
                en[0] = ok ? IN2H[c2a * VOX + rb + ex] : 0u;
                en[1] = ok ? IN2H[c2b * VOX + rb + ex] : 0u;
            }

            // 6-wide half2 windows via shuffle
            uint32_t wv0[6], wv1[6];
            wv0[1] = v[0].x; wv0[2] = v[0].y; wv0[3] = v[0].z; wv0[4] = v[0].w;
            wv1[1] = v[1].x; wv1[2] = v[1].y; wv1[3] = v[1].z; wv1[4] = v[1].w;
            {
                const uint32_t up0 = __shfl_up_sync(0xffffffffu, v[0].w, 4);
                const uint32_t up1 = __shfl_up_sync(0xffffffffu, v[1].w, 4);
                const uint32_t dn0 = __shfl_down_sync(0xffffffffu, v[0].x, 4);
                const uint32_t dn1 = __shfl_down_sync(0xffffffffu, v[1].x, 4);
                wv0[0] = (tg == 0) ? (lo_real ? e[0] : 0u) : up0;
                wv1[0] = (tg == 0) ? (lo_real ? e[1] : 0u) : up1;
                wv0[5] = (tg == 7) ? (lo_real ? 0u : e[0]) : dn0;
                wv1[5] = (tg == 7) ? (lo_real ? 0u : e[1]) : dn1;
            }

#pragma unroll
            for (int dx = 0; dx < 3; dx++) {
                const int off = it * 3 + dx;
                const int chunk = off * 2 + kc;
                const uint4 wA = wfs[chunk * 64 + lane];
                const uint4 wB = wfs[chunk * 64 + 32 + lane];

#pragma unroll
                for (int mt = 0; mt < 2; mt++) {
                    const int p0 = 2 * mt, p1 = 2 * mt + 1;
                    const uint32_t a0 = hmul2(i1A[p0], wv0[dx + p0]);
                    const uint32_t a1 = hmul2(i1A[p1], wv0[dx + p1]);
                    const uint32_t a2 = hmul2(i1B[p0], wv1[dx + p0]);
                    const uint32_t a3 = hmul2(i1B[p1], wv1[dx + p1]);
                    float* acc = mt ? acc1 : acc0;
                    mma16816(acc + 0,  a0, a1, a2, a3, wA.x, wA.y);
                    mma16816(acc + 4,  a0, a1, a2, a3, wA.z, wA.w);
                    mma16816(acc + 8,  a0, a1, a2, a3, wB.x, wB.y);
                    mma16816(acc + 12, a0, a1, a2, a3, wB.z, wB.w);
                }
            }

            v[0] = vn[0]; v[1] = vn[1]; e[0] = en[0]; e[1] = en[1];
        }
    }

    // epilogue: o = nt*8 + 2tk (+1); x = 4tg..4tg+3 -> one STG.128 per o
#pragma unroll
    for (int nt = 0; nt < 4; nt++) {
        const int o0 = nt * 8 + 2 * tk;
        const int o1 = o0 + 1;
        if (o0 < NOFF_) {
            const float b = __ldg(bias + o0);
            const float4 r = make_float4(acc0[nt * 4 + 0] + b, acc0[nt * 4 + 2] + b,
                                         acc1[nt * 4 + 0] + b, acc1[nt * 4 + 2] + b);
            *reinterpret_cast<float4*>(out + o0 * VOX + vbase + 4 * tg) = r;
        }
        if (o1 < NOFF_) {
            const float b = __ldg(bias + o1);
            const float4 r = make_float4(acc0[nt * 4 + 1] + b, acc0[nt * 4 + 3] + b,
                                         acc1[nt * 4 + 1] + b, acc1[nt * 4 + 3] + b);
            *reinterpret_cast<float4*>(out + o1 * VOX + vbase + 4 * tg) = r;
        }
    }
}

extern "C" void kernel_launch(void* const* d_in, const int* in_sizes, int n_in,
                              void* d_out, int out_size) {
    const float* in1 = (const float*)d_in[0];
    const float* in2 = (const float*)d_in[1];
    const float* w   = (const float*)d_in[2];
    const float* b   = (const float*)d_in[3];
    float* out = (float*)d_out;

    convert_inputs<<<(2 * PAIRS * VOX / 4 + 255) / 256, 256>>>(in1, in2);
    stage_weights<<<(WQ_ELEMS + 255) / 256, 256>>>(w);

    const int smem = WQ_ELEMS * (int)sizeof(uint4);   // 55296
    cudaFuncSetAttribute(corr_mma,
                         cudaFuncAttributeMaxDynamicSharedMemorySize, smem);
    corr_mma<<<1024, TPB, smem>>>(b, out);
}